// round 15
// baseline (speedup 1.0000x reference)
#include <cuda_runtime.h>
#include <math.h>
#include <stdint.h>

#define B 4
#define T 2048
#define DMODEL 2048
#define NH 16
#define KVH 4
#define DK 128
#define GQA (NH / KVH)

__device__ float g_Q[(size_t)B * T * DMODEL];
__device__ float g_K[(size_t)B * T * KVH * DK];
__device__ float g_V[(size_t)B * T * KVH * DK];
__device__ float g_AO[(size_t)B * T * DMODEL];

__device__ __forceinline__ unsigned f2tf32(float x) {
    unsigned r;
    asm("cvt.rna.tf32.f32 %0, %1;" : "=r"(r) : "f"(x));
    return r;
}

__device__ __forceinline__ void mma_tf32(float c[4], const unsigned a[4], const unsigned b[2]) {
    asm volatile(
        "mma.sync.aligned.m16n8k8.row.col.f32.tf32.tf32.f32 "
        "{%0,%1,%2,%3}, {%4,%5,%6,%7}, {%8,%9}, {%0,%1,%2,%3};"
        : "+f"(c[0]), "+f"(c[1]), "+f"(c[2]), "+f"(c[3])
        : "r"(a[0]), "r"(a[1]), "r"(a[2]), "r"(a[3]), "r"(b[0]), "r"(b[1]));
}

__device__ __forceinline__ uint32_t smem_u32(const void* p) {
    return (uint32_t)__cvta_generic_to_shared(p);
}
#define CP_ASYNC16(dst, src) \
    asm volatile("cp.async.cg.shared.global [%0], [%1], 16;" :: "r"(dst), "l"(src))
#define CP_COMMIT() asm volatile("cp.async.commit_group;")
#define CP_WAIT1()  asm volatile("cp.async.wait_group 1;")
#define CP_WAIT0()  asm volatile("cp.async.wait_group 0;")

// ---------------------------------------------------------------------------
// C[M,N] = A[M,K] * W[N,K]^T, tf32 mma, cp.async 2-stage pipeline.
// EXACT round-8 version: floats in SMEM, cvt at frag load, fused RoPE.
// ---------------------------------------------------------------------------
__global__ __launch_bounds__(256) void gemm_tf32(
    const float* __restrict__ A,
    const float* __restrict__ Wa, const float* __restrict__ Wb,
    float* __restrict__ Ca, float* __restrict__ Cb,
    int M, int N, int K, int ropeA, int ropeB)
{
    __shared__ float As[2][128][20];
    __shared__ float Bs[2][128][20];

    const float* __restrict__ W = blockIdx.z ? Wb : Wa;
    float* __restrict__ C       = blockIdx.z ? Cb : Ca;
    const int rope              = blockIdx.z ? ropeB : ropeA;

    const int tid  = threadIdx.x;
    const int bm   = blockIdx.y * 128;
    const int bn   = blockIdx.x * 128;
    const int warp = tid >> 5, lane = tid & 31;
    const int wm   = (warp & 1) * 64;
    const int wn   = (warp >> 1) * 32;
    const int gID  = lane >> 2, tig = lane & 3;

    float acc[4][4][4];
#pragma unroll
    for (int i = 0; i < 4; ++i)
#pragma unroll
        for (int j = 0; j < 4; ++j)
#pragma unroll
            for (int q = 0; q < 4; ++q) acc[i][j][q] = 0.f;

    const int ntiles = K >> 4;

    {
#pragma unroll
        for (int i = 0; i < 2; ++i) {
            const int idx = tid + i * 256;
            const int row = idx >> 2;
            const int c   = (idx & 3) << 2;
            CP_ASYNC16(smem_u32(&As[0][row][c]), A + (size_t)(bm + row) * K + c);
            CP_ASYNC16(smem_u32(&Bs[0][row][c]), W + (size_t)(bn + row) * K + c);
        }
        CP_COMMIT();
    }

    for (int tt = 0; tt < ntiles; ++tt) {
        const int st = tt & 1;
        if (tt + 1 < ntiles) {
            const int k0 = (tt + 1) << 4;
            const int s1 = (tt + 1) & 1;
#pragma unroll
            for (int i = 0; i < 2; ++i) {
                const int idx = tid + i * 256;
                const int row = idx >> 2;
                const int c   = (idx & 3) << 2;
                CP_ASYNC16(smem_u32(&As[s1][row][c]), A + (size_t)(bm + row) * K + k0 + c);
                CP_ASYNC16(smem_u32(&Bs[s1][row][c]), W + (size_t)(bn + row) * K + k0 + c);
            }
            CP_COMMIT();
            CP_WAIT1();
        } else {
            CP_WAIT0();
        }
        __syncthreads();

#pragma unroll
        for (int ks = 0; ks < 2; ++ks) {
            const int kk = ks * 8;
            unsigned af[4][4], bf[4][2];
#pragma unroll
            for (int mt = 0; mt < 4; ++mt) {
                const int m0 = wm + mt * 16;
                af[mt][0] = f2tf32(As[st][m0 + gID    ][kk + tig]);
                af[mt][1] = f2tf32(As[st][m0 + gID + 8][kk + tig]);
                af[mt][2] = f2tf32(As[st][m0 + gID    ][kk + tig + 4]);
                af[mt][3] = f2tf32(As[st][m0 + gID + 8][kk + tig + 4]);
            }
#pragma unroll
            for (int nt = 0; nt < 4; ++nt) {
                const int n0 = wn + nt * 8;
                bf[nt][0] = f2tf32(Bs[st][n0 + gID][kk + tig]);
                bf[nt][1] = f2tf32(Bs[st][n0 + gID][kk + tig + 4]);
            }
#pragma unroll
            for (int mt = 0; mt < 4; ++mt)
#pragma unroll
                for (int nt = 0; nt < 4; ++nt)
                    mma_tf32(acc[mt][nt], af[mt], bf[nt]);
        }
        __syncthreads();
    }

    if (rope) {
#pragma unroll
        for (int nt = 0; nt < 4; ++nt) {
            const int col  = bn + wn + nt * 8 + tig * 2;
            const float e  = (float)(col & 127) * (1.0f / 128.0f);
            const float inv_freq = exp2f(-e * 13.2877123795494f);   // log2(10000)
#pragma unroll
            for (int mt = 0; mt < 4; ++mt) {
                const int row0 = bm + wm + mt * 16 + gID;
                const int t0   = row0 & (T - 1);
                const int t1   = (row0 + 8) & (T - 1);
                float s0, c0, s1, c1;
                sincosf((float)t0 * inv_freq, &s0, &c0);
                sincosf((float)t1 * inv_freq, &s1, &c1);
                const float x1a = acc[mt][nt][0], x2a = acc[mt][nt][1];
                acc[mt][nt][0] = x1a * c0 - x2a * s0;
                acc[mt][nt][1] = x1a * s0 + x2a * c0;
                const float x1b = acc[mt][nt][2], x2b = acc[mt][nt][3];
                acc[mt][nt][2] = x1b * c1 - x2b * s1;
                acc[mt][nt][3] = x1b * s1 + x2b * c1;
            }
        }
    }

#pragma unroll
    for (int mt = 0; mt < 4; ++mt) {
#pragma unroll
        for (int nt = 0; nt < 4; ++nt) {
            const int row0 = bm + wm + mt * 16 + gID;
            const int col  = bn + wn + nt * 8 + tig * 2;
            float2* p0 = (float2*)(C + (size_t)row0 * N + col);
            float2* p1 = (float2*)(C + (size_t)(row0 + 8) * N + col);
            *p0 = make_float2(acc[mt][nt][0], acc[mt][nt][1]);
            *p1 = make_float2(acc[mt][nt][2], acc[mt][nt][3]);
        }
    }
}

// ---------------------------------------------------------------------------
// Tensor-core causal GQA flash attention, 64q x 64k tiles, heavy-first 1-D
// grid (round-14 win). NEW: P buffer ALIASES Ks rows [warp*16, warp*16+16)
// (Ks is dead between the QK^T mma and next tile's staging) -> SMEM 84.6KB
// -> 67KB -> 3 blocks/SM (+50% warps). A __syncthreads separates the last
// Ks b-frag read from the first P store.
// ---------------------------------------------------------------------------
#define KS_STRIDE 132
#define VS_STRIDE 136
#define ATTN_SMEM_WORDS (64 * KS_STRIDE + 64 * VS_STRIDE)
#define ATTN_SMEM_BYTES (ATTN_SMEM_WORDS * 4)   // 68608

__global__ __launch_bounds__(128, 3) void attn_mma(
    const float* __restrict__ Q, const float* __restrict__ K,
    const float* __restrict__ V, float* __restrict__ O)
{
    extern __shared__ unsigned dsm[];
    unsigned (*Ks)[KS_STRIDE] = (unsigned(*)[KS_STRIDE])dsm;
    unsigned (*Vs)[VS_STRIDE] = (unsigned(*)[VS_STRIDE])(dsm + 64 * KS_STRIDE);

    const int bid   = blockIdx.x;
    const int qtile = (T / 64 - 1) - (bid >> 6);   // heavy q-tiles first
    const int bh    = bid & 63;
    const int b     = bh / NH;
    const int h     = bh % NH;
    const int kvh   = h / GQA;

    const int tid  = threadIdx.x;
    const int warp = tid >> 5, lane = tid & 31;
    const int gID  = lane >> 2, tig = lane & 3;
    const int prow = warp * 16;                    // P alias row base in Ks

    const int qrow0 = qtile * 64;
    const float scale = 0.08838834764831845f;   // 1/sqrt(128)

    {
        const float* Qg = Q + ((size_t)(b * T + qrow0)) * DMODEL + h * DK;
#pragma unroll
        for (int i = 0; i < 16; ++i) {
            const int idx = i * 128 + tid;
            const int r   = idx >> 5;
            const int c4  = (idx & 31) << 2;
            const float4 v = *(const float4*)(Qg + (size_t)r * DMODEL + c4);
            *(uint4*)&Ks[r][c4] = make_uint4(
                f2tf32(v.x * scale), f2tf32(v.y * scale),
                f2tf32(v.z * scale), f2tf32(v.w * scale));
        }
    }
    __syncthreads();

    unsigned qa[16][4];
    {
        const int m0 = warp * 16;
#pragma unroll
        for (int kk = 0; kk < 16; ++kk) {
            qa[kk][0] = Ks[m0 + gID    ][kk * 8 + tig];
            qa[kk][1] = Ks[m0 + gID + 8][kk * 8 + tig];
            qa[kk][2] = Ks[m0 + gID    ][kk * 8 + tig + 4];
            qa[kk][3] = Ks[m0 + gID + 8][kk * 8 + tig + 4];
        }
    }

    float oacc[16][4];
#pragma unroll
    for (int i = 0; i < 16; ++i)
#pragma unroll
        for (int j = 0; j < 4; ++j) oacc[i][j] = 0.f;

    float m0s = -INFINITY, m1s = -INFINITY, l0 = 0.f, l1 = 0.f;
    const int rowg0 = qrow0 + warp * 16 + gID;
    const int rowg1 = rowg0 + 8;

    const size_t kvStride = (size_t)KVH * DK;   // 512
    const int ntiles = qtile + 1;

    for (int tile = 0; tile < ntiles; ++tile) {
        const int kt = tile * 64;
        __syncthreads();   // prior Ks(P)/Vs readers done before restaging
        {
            const float* Kg = K + ((size_t)(b * T + kt)) * kvStride + kvh * DK;
            const float* Vg = V + ((size_t)(b * T + kt)) * kvStride + kvh * DK;
#pragma unroll
            for (int i = 0; i < 16; ++i) {
                const int idx = i * 128 + tid;
                const int r   = idx >> 5;
                const int c4  = (idx & 31) << 2;
                const float4 kv = *(const float4*)(Kg + (size_t)r * kvStride + c4);
                const float4 vv = *(const float4*)(Vg + (size_t)r * kvStride + c4);
                *(uint4*)&Ks[r][c4] = make_uint4(f2tf32(kv.x), f2tf32(kv.y),
                                                 f2tf32(kv.z), f2tf32(kv.w));
                *(uint4*)&Vs[r][c4] = make_uint4(f2tf32(vv.x), f2tf32(vv.y),
                                                 f2tf32(vv.z), f2tf32(vv.w));
            }
        }
        __syncthreads();

        // S = Q*K^T  (m16 x n64, k=128)
        float sacc[8][4];
#pragma unroll
        for (int nt = 0; nt < 8; ++nt)
#pragma unroll
            for (int e = 0; e < 4; ++e) sacc[nt][e] = 0.f;

#pragma unroll
        for (int kk = 0; kk < 16; ++kk) {
            unsigned bfr[8][2];
#pragma unroll
            for (int nt = 0; nt < 8; ++nt) {
                bfr[nt][0] = Ks[nt * 8 + gID][kk * 8 + tig];
                bfr[nt][1] = Ks[nt * 8 + gID][kk * 8 + tig + 4];
            }
#pragma unroll
            for (int nt = 0; nt < 8; ++nt)
                mma_tf32(sacc[nt], qa[kk], bfr[nt]);
        }

        __syncthreads();   // ALL warps done reading Ks before P aliases it

        const bool diag = (tile == ntiles - 1);
        float rmax0 = -INFINITY, rmax1 = -INFINITY;
#pragma unroll
        for (int nt = 0; nt < 8; ++nt) {
            if (diag) {
                const int colg = kt + nt * 8 + tig * 2;
                if (colg     > rowg0) sacc[nt][0] = -1e30f;
                if (colg + 1 > rowg0) sacc[nt][1] = -1e30f;
                if (colg     > rowg1) sacc[nt][2] = -1e30f;
                if (colg + 1 > rowg1) sacc[nt][3] = -1e30f;
            }
            rmax0 = fmaxf(rmax0, fmaxf(sacc[nt][0], sacc[nt][1]));
            rmax1 = fmaxf(rmax1, fmaxf(sacc[nt][2], sacc[nt][3]));
        }
        rmax0 = fmaxf(rmax0, __shfl_xor_sync(0xffffffffu, rmax0, 1));
        rmax0 = fmaxf(rmax0, __shfl_xor_sync(0xffffffffu, rmax0, 2));
        rmax1 = fmaxf(rmax1, __shfl_xor_sync(0xffffffffu, rmax1, 1));
        rmax1 = fmaxf(rmax1, __shfl_xor_sync(0xffffffffu, rmax1, 2));

        const float mn0 = fmaxf(m0s, rmax0);
        const float mn1 = fmaxf(m1s, rmax1);
        const float corr0 = __expf(m0s - mn0);
        const float corr1 = __expf(m1s - mn1);
        m0s = mn0; m1s = mn1;

        float psum0 = 0.f, psum1 = 0.f;
#pragma unroll
        for (int nt = 0; nt < 8; ++nt) {
            const float p0 = __expf(sacc[nt][0] - mn0);
            const float p1 = __expf(sacc[nt][1] - mn0);
            const float p2 = __expf(sacc[nt][2] - mn1);
            const float p3 = __expf(sacc[nt][3] - mn1);
            psum0 += p0 + p1;
            psum1 += p2 + p3;
            Ks[prow + gID    ][nt * 8 + tig * 2    ] = f2tf32(p0);
            Ks[prow + gID    ][nt * 8 + tig * 2 + 1] = f2tf32(p1);
            Ks[prow + gID + 8][nt * 8 + tig * 2    ] = f2tf32(p2);
            Ks[prow + gID + 8][nt * 8 + tig * 2 + 1] = f2tf32(p3);
        }
        psum0 += __shfl_xor_sync(0xffffffffu, psum0, 1);
        psum0 += __shfl_xor_sync(0xffffffffu, psum0, 2);
        psum1 += __shfl_xor_sync(0xffffffffu, psum1, 1);
        psum1 += __shfl_xor_sync(0xffffffffu, psum1, 2);
        l0 = l0 * corr0 + psum0;
        l1 = l1 * corr1 + psum1;

#pragma unroll
        for (int nt = 0; nt < 16; ++nt) {
            oacc[nt][0] *= corr0; oacc[nt][1] *= corr0;
            oacc[nt][2] *= corr1; oacc[nt][3] *= corr1;
        }
        __syncwarp();   // P stores visible to all lanes of this warp

        // O += P*V  (m16 x n128, k=64); P read from the Ks alias rows
#pragma unroll
        for (int kk = 0; kk < 8; ++kk) {
            unsigned pa[4];
            pa[0] = Ks[prow + gID    ][kk * 8 + tig];
            pa[1] = Ks[prow + gID + 8][kk * 8 + tig];
            pa[2] = Ks[prow + gID    ][kk * 8 + tig + 4];
            pa[3] = Ks[prow + gID + 8][kk * 8 + tig + 4];
#pragma unroll
            for (int nt = 0; nt < 16; ++nt) {
                unsigned bv[2];
                bv[0] = Vs[kk * 8 + tig    ][nt * 8 + gID];
                bv[1] = Vs[kk * 8 + tig + 4][nt * 8 + gID];
                mma_tf32(oacc[nt], pa, bv);
            }
        }
    }

    const float il0 = 1.f / l0;
    const float il1 = 1.f / l1;
    float* Og = O + ((size_t)(b * T + rowg0)) * DMODEL + h * DK;
#pragma unroll
    for (int nt = 0; nt < 16; ++nt) {
        const int col = nt * 8 + tig * 2;
        *(float2*)(Og + col) =
            make_float2(oacc[nt][0] * il0, oacc[nt][1] * il0);
        *(float2*)(Og + (size_t)8 * DMODEL + col) =
            make_float2(oacc[nt][2] * il1, oacc[nt][3] * il1);
    }
}

// ---------------------------------------------------------------------------
extern "C" void kernel_launch(void* const* d_in, const int* in_sizes, int n_in,
                              void* d_out, int out_size)
{
    (void)in_sizes; (void)n_in; (void)out_size;
    const float* x  = (const float*)d_in[0];
    const float* Wq = (const float*)d_in[2];
    const float* Wk = (const float*)d_in[3];
    const float* Wv = (const float*)d_in[4];
    const float* Wo = (const float*)d_in[5];
    float* out = (float*)d_out;

    float *Qb, *Kb, *Vb, *AO;
    cudaGetSymbolAddress((void**)&Qb, g_Q);
    cudaGetSymbolAddress((void**)&Kb, g_K);
    cudaGetSymbolAddress((void**)&Vb, g_V);
    cudaGetSymbolAddress((void**)&AO, g_AO);

    cudaFuncSetAttribute(attn_mma, cudaFuncAttributeMaxDynamicSharedMemorySize,
                         ATTN_SMEM_BYTES);

    const int M = B * T;   // 8192

    // Fork: Q-projection and KV-projection run concurrently (independent).
    cudaStream_t s2;
    cudaEvent_t evFork, evJoin;
    cudaStreamCreateWithFlags(&s2, cudaStreamNonBlocking);
    cudaEventCreateWithFlags(&evFork, cudaEventDisableTiming);
    cudaEventCreateWithFlags(&evJoin, cudaEventDisableTiming);

    cudaEventRecord(evFork, 0);
    cudaStreamWaitEvent(s2, evFork, 0);

    gemm_tf32<<<dim3((KVH * DK) / 128, M / 128, 2), 256, 0, s2>>>(
        x, Wk, Wv, Kb, Vb, M, KVH * DK, DMODEL, 1, 0);
    cudaEventRecord(evJoin, s2);

    gemm_tf32<<<dim3(DMODEL / 128, M / 128, 1), 256>>>(
        x, Wq, Wq, Qb, Qb, M, DMODEL, DMODEL, 1, 1);

    cudaStreamWaitEvent(0, evJoin, 0);

    attn_mma<<<dim3((T / 64) * B * NH), 128, ATTN_SMEM_BYTES>>>(Qb, Kb, Vb, AO);

    gemm_tf32<<<dim3(DMODEL / 128, M / 128, 1), 256>>>(
        AO, Wo, Wo, out, out, M, DMODEL, DMODEL, 0, 0);

    cudaEventDestroy(evFork);
    cudaEventDestroy(evJoin);
    cudaStreamDestroy(s2);
}

// round 16
// speedup vs baseline: 1.0401x; 1.0401x over previous
#include <cuda_runtime.h>
#include <math.h>
#include <stdint.h>

#define B 4
#define T 2048
#define DMODEL 2048
#define NH 16
#define KVH 4
#define DK 128
#define GQA (NH / KVH)

__device__ float g_Q[(size_t)B * T * DMODEL];
__device__ float g_K[(size_t)B * T * KVH * DK];
__device__ float g_V[(size_t)B * T * KVH * DK];
__device__ float g_AO[(size_t)B * T * DMODEL];

__device__ __forceinline__ unsigned f2tf32(float x) {
    unsigned r;
    asm("cvt.rna.tf32.f32 %0, %1;" : "=r"(r) : "f"(x));
    return r;
}

__device__ __forceinline__ void mma_tf32(float c[4], const unsigned a[4], const unsigned b[2]) {
    asm volatile(
        "mma.sync.aligned.m16n8k8.row.col.f32.tf32.tf32.f32 "
        "{%0,%1,%2,%3}, {%4,%5,%6,%7}, {%8,%9}, {%0,%1,%2,%3};"
        : "+f"(c[0]), "+f"(c[1]), "+f"(c[2]), "+f"(c[3])
        : "r"(a[0]), "r"(a[1]), "r"(a[2]), "r"(a[3]), "r"(b[0]), "r"(b[1]));
}

__device__ __forceinline__ uint32_t smem_u32(const void* p) {
    return (uint32_t)__cvta_generic_to_shared(p);
}
#define CP_ASYNC16(dst, src) \
    asm volatile("cp.async.cg.shared.global [%0], [%1], 16;" :: "r"(dst), "l"(src))
#define CP_COMMIT() asm volatile("cp.async.commit_group;")
#define CP_WAIT1()  asm volatile("cp.async.wait_group 1;")
#define CP_WAIT0()  asm volatile("cp.async.wait_group 0;")

// ---------------------------------------------------------------------------
// C[M,N] = A[M,K] * W[N,K]^T, tf32 mma, cp.async 2-stage pipeline.
// EXACT round-8 version: floats in SMEM, cvt at frag load, fused RoPE.
// ---------------------------------------------------------------------------
__global__ __launch_bounds__(256) void gemm_tf32(
    const float* __restrict__ A,
    const float* __restrict__ Wa, const float* __restrict__ Wb,
    float* __restrict__ Ca, float* __restrict__ Cb,
    int M, int N, int K, int ropeA, int ropeB)
{
    __shared__ float As[2][128][20];
    __shared__ float Bs[2][128][20];

    const float* __restrict__ W = blockIdx.z ? Wb : Wa;
    float* __restrict__ C       = blockIdx.z ? Cb : Ca;
    const int rope              = blockIdx.z ? ropeB : ropeA;

    const int tid  = threadIdx.x;
    const int bm   = blockIdx.y * 128;
    const int bn   = blockIdx.x * 128;
    const int warp = tid >> 5, lane = tid & 31;
    const int wm   = (warp & 1) * 64;
    const int wn   = (warp >> 1) * 32;
    const int gID  = lane >> 2, tig = lane & 3;

    float acc[4][4][4];
#pragma unroll
    for (int i = 0; i < 4; ++i)
#pragma unroll
        for (int j = 0; j < 4; ++j)
#pragma unroll
            for (int q = 0; q < 4; ++q) acc[i][j][q] = 0.f;

    const int ntiles = K >> 4;

    {
#pragma unroll
        for (int i = 0; i < 2; ++i) {
            const int idx = tid + i * 256;
            const int row = idx >> 2;
            const int c   = (idx & 3) << 2;
            CP_ASYNC16(smem_u32(&As[0][row][c]), A + (size_t)(bm + row) * K + c);
            CP_ASYNC16(smem_u32(&Bs[0][row][c]), W + (size_t)(bn + row) * K + c);
        }
        CP_COMMIT();
    }

    for (int tt = 0; tt < ntiles; ++tt) {
        const int st = tt & 1;
        if (tt + 1 < ntiles) {
            const int k0 = (tt + 1) << 4;
            const int s1 = (tt + 1) & 1;
#pragma unroll
            for (int i = 0; i < 2; ++i) {
                const int idx = tid + i * 256;
                const int row = idx >> 2;
                const int c   = (idx & 3) << 2;
                CP_ASYNC16(smem_u32(&As[s1][row][c]), A + (size_t)(bm + row) * K + k0 + c);
                CP_ASYNC16(smem_u32(&Bs[s1][row][c]), W + (size_t)(bn + row) * K + k0 + c);
            }
            CP_COMMIT();
            CP_WAIT1();
        } else {
            CP_WAIT0();
        }
        __syncthreads();

#pragma unroll
        for (int ks = 0; ks < 2; ++ks) {
            const int kk = ks * 8;
            unsigned af[4][4], bf[4][2];
#pragma unroll
            for (int mt = 0; mt < 4; ++mt) {
                const int m0 = wm + mt * 16;
                af[mt][0] = f2tf32(As[st][m0 + gID    ][kk + tig]);
                af[mt][1] = f2tf32(As[st][m0 + gID + 8][kk + tig]);
                af[mt][2] = f2tf32(As[st][m0 + gID    ][kk + tig + 4]);
                af[mt][3] = f2tf32(As[st][m0 + gID + 8][kk + tig + 4]);
            }
#pragma unroll
            for (int nt = 0; nt < 4; ++nt) {
                const int n0 = wn + nt * 8;
                bf[nt][0] = f2tf32(Bs[st][n0 + gID][kk + tig]);
                bf[nt][1] = f2tf32(Bs[st][n0 + gID][kk + tig + 4]);
            }
#pragma unroll
            for (int mt = 0; mt < 4; ++mt)
#pragma unroll
                for (int nt = 0; nt < 4; ++nt)
                    mma_tf32(acc[mt][nt], af[mt], bf[nt]);
        }
        __syncthreads();
    }

    if (rope) {
#pragma unroll
        for (int nt = 0; nt < 4; ++nt) {
            const int col  = bn + wn + nt * 8 + tig * 2;
            const float e  = (float)(col & 127) * (1.0f / 128.0f);
            const float inv_freq = exp2f(-e * 13.2877123795494f);   // log2(10000)
#pragma unroll
            for (int mt = 0; mt < 4; ++mt) {
                const int row0 = bm + wm + mt * 16 + gID;
                const int t0   = row0 & (T - 1);
                const int t1   = (row0 + 8) & (T - 1);
                float s0, c0, s1, c1;
                sincosf((float)t0 * inv_freq, &s0, &c0);
                sincosf((float)t1 * inv_freq, &s1, &c1);
                const float x1a = acc[mt][nt][0], x2a = acc[mt][nt][1];
                acc[mt][nt][0] = x1a * c0 - x2a * s0;
                acc[mt][nt][1] = x1a * s0 + x2a * c0;
                const float x1b = acc[mt][nt][2], x2b = acc[mt][nt][3];
                acc[mt][nt][2] = x1b * c1 - x2b * s1;
                acc[mt][nt][3] = x1b * s1 + x2b * c1;
            }
        }
    }

#pragma unroll
    for (int mt = 0; mt < 4; ++mt) {
#pragma unroll
        for (int nt = 0; nt < 4; ++nt) {
            const int row0 = bm + wm + mt * 16 + gID;
            const int col  = bn + wn + nt * 8 + tig * 2;
            float2* p0 = (float2*)(C + (size_t)row0 * N + col);
            float2* p1 = (float2*)(C + (size_t)(row0 + 8) * N + col);
            *p0 = make_float2(acc[mt][nt][0], acc[mt][nt][1]);
            *p1 = make_float2(acc[mt][nt][2], acc[mt][nt][3]);
        }
    }
}

// ---------------------------------------------------------------------------
// Tensor-core causal GQA flash attention, 64q x 64k tiles — EXACT round-14
// compute (1696.9us best), parameterized by batch offset + count for the
// attention/O-GEMM pipeline. Heavy-first 1-D grid within each half.
// ---------------------------------------------------------------------------
#define KS_STRIDE 132
#define VS_STRIDE 136
#define PS_STRIDE 68
#define ATTN_SMEM_WORDS (64 * KS_STRIDE + 64 * VS_STRIDE + 4 * 16 * PS_STRIDE)
#define ATTN_SMEM_BYTES (ATTN_SMEM_WORDS * 4)

__global__ __launch_bounds__(128) void attn_mma(
    const float* __restrict__ Q, const float* __restrict__ K,
    const float* __restrict__ V, float* __restrict__ O,
    int b_off, int nb)   // batches [b_off, b_off+nb)
{
    extern __shared__ unsigned dsm[];
    unsigned (*Ks)[KS_STRIDE] = (unsigned(*)[KS_STRIDE])dsm;
    unsigned (*Vs)[VS_STRIDE] = (unsigned(*)[VS_STRIDE])(dsm + 64 * KS_STRIDE);
    unsigned (*Ps)[16][PS_STRIDE] =
        (unsigned(*)[16][PS_STRIDE])(dsm + 64 * KS_STRIDE + 64 * VS_STRIDE);

    const int bid    = blockIdx.x;
    const int combos = nb * NH;                       // (batch, head) combos
    const int qtile  = (T / 64 - 1) - (bid / combos); // heavy q-tiles first
    const int bh     = bid % combos;
    const int b      = b_off + bh / NH;
    const int h      = bh % NH;
    const int kvh    = h / GQA;

    const int tid  = threadIdx.x;
    const int warp = tid >> 5, lane = tid & 31;
    const int gID  = lane >> 2, tig = lane & 3;

    const int qrow0 = qtile * 64;
    const float scale = 0.08838834764831845f;   // 1/sqrt(128)

    {
        const float* Qg = Q + ((size_t)(b * T + qrow0)) * DMODEL + h * DK;
#pragma unroll
        for (int i = 0; i < 16; ++i) {
            const int idx = i * 128 + tid;
            const int r   = idx >> 5;
            const int c4  = (idx & 31) << 2;
            const float4 v = *(const float4*)(Qg + (size_t)r * DMODEL + c4);
            *(uint4*)&Ks[r][c4] = make_uint4(
                f2tf32(v.x * scale), f2tf32(v.y * scale),
                f2tf32(v.z * scale), f2tf32(v.w * scale));
        }
    }
    __syncthreads();

    unsigned qa[16][4];
    {
        const int m0 = warp * 16;
#pragma unroll
        for (int kk = 0; kk < 16; ++kk) {
            qa[kk][0] = Ks[m0 + gID    ][kk * 8 + tig];
            qa[kk][1] = Ks[m0 + gID + 8][kk * 8 + tig];
            qa[kk][2] = Ks[m0 + gID    ][kk * 8 + tig + 4];
            qa[kk][3] = Ks[m0 + gID + 8][kk * 8 + tig + 4];
        }
    }

    float oacc[16][4];
#pragma unroll
    for (int i = 0; i < 16; ++i)
#pragma unroll
        for (int j = 0; j < 4; ++j) oacc[i][j] = 0.f;

    float m0s = -INFINITY, m1s = -INFINITY, l0 = 0.f, l1 = 0.f;
    const int rowg0 = qrow0 + warp * 16 + gID;
    const int rowg1 = rowg0 + 8;

    const size_t kvStride = (size_t)KVH * DK;   // 512
    const int ntiles = qtile + 1;

    for (int tile = 0; tile < ntiles; ++tile) {
        const int kt = tile * 64;
        __syncthreads();
        {
            const float* Kg = K + ((size_t)(b * T + kt)) * kvStride + kvh * DK;
            const float* Vg = V + ((size_t)(b * T + kt)) * kvStride + kvh * DK;
#pragma unroll
            for (int i = 0; i < 16; ++i) {
                const int idx = i * 128 + tid;
                const int r   = idx >> 5;
                const int c4  = (idx & 31) << 2;
                const float4 kv = *(const float4*)(Kg + (size_t)r * kvStride + c4);
                const float4 vv = *(const float4*)(Vg + (size_t)r * kvStride + c4);
                *(uint4*)&Ks[r][c4] = make_uint4(f2tf32(kv.x), f2tf32(kv.y),
                                                 f2tf32(kv.z), f2tf32(kv.w));
                *(uint4*)&Vs[r][c4] = make_uint4(f2tf32(vv.x), f2tf32(vv.y),
                                                 f2tf32(vv.z), f2tf32(vv.w));
            }
        }
        __syncthreads();

        float sacc[8][4];
#pragma unroll
        for (int nt = 0; nt < 8; ++nt)
#pragma unroll
            for (int e = 0; e < 4; ++e) sacc[nt][e] = 0.f;

#pragma unroll
        for (int kk = 0; kk < 16; ++kk) {
            unsigned bfr[8][2];
#pragma unroll
            for (int nt = 0; nt < 8; ++nt) {
                bfr[nt][0] = Ks[nt * 8 + gID][kk * 8 + tig];
                bfr[nt][1] = Ks[nt * 8 + gID][kk * 8 + tig + 4];
            }
#pragma unroll
            for (int nt = 0; nt < 8; ++nt)
                mma_tf32(sacc[nt], qa[kk], bfr[nt]);
        }

        const bool diag = (tile == ntiles - 1);
        float rmax0 = -INFINITY, rmax1 = -INFINITY;
#pragma unroll
        for (int nt = 0; nt < 8; ++nt) {
            if (diag) {
                const int colg = kt + nt * 8 + tig * 2;
                if (colg     > rowg0) sacc[nt][0] = -1e30f;
                if (colg + 1 > rowg0) sacc[nt][1] = -1e30f;
                if (colg     > rowg1) sacc[nt][2] = -1e30f;
                if (colg + 1 > rowg1) sacc[nt][3] = -1e30f;
            }
            rmax0 = fmaxf(rmax0, fmaxf(sacc[nt][0], sacc[nt][1]));
            rmax1 = fmaxf(rmax1, fmaxf(sacc[nt][2], sacc[nt][3]));
        }
        rmax0 = fmaxf(rmax0, __shfl_xor_sync(0xffffffffu, rmax0, 1));
        rmax0 = fmaxf(rmax0, __shfl_xor_sync(0xffffffffu, rmax0, 2));
        rmax1 = fmaxf(rmax1, __shfl_xor_sync(0xffffffffu, rmax1, 1));
        rmax1 = fmaxf(rmax1, __shfl_xor_sync(0xffffffffu, rmax1, 2));

        const float mn0 = fmaxf(m0s, rmax0);
        const float mn1 = fmaxf(m1s, rmax1);
        const float corr0 = __expf(m0s - mn0);
        const float corr1 = __expf(m1s - mn1);
        m0s = mn0; m1s = mn1;

        __syncwarp();
        float psum0 = 0.f, psum1 = 0.f;
#pragma unroll
        for (int nt = 0; nt < 8; ++nt) {
            const float p0 = __expf(sacc[nt][0] - mn0);
            const float p1 = __expf(sacc[nt][1] - mn0);
            const float p2 = __expf(sacc[nt][2] - mn1);
            const float p3 = __expf(sacc[nt][3] - mn1);
            psum0 += p0 + p1;
            psum1 += p2 + p3;
            Ps[warp][gID    ][nt * 8 + tig * 2    ] = f2tf32(p0);
            Ps[warp][gID    ][nt * 8 + tig * 2 + 1] = f2tf32(p1);
            Ps[warp][gID + 8][nt * 8 + tig * 2    ] = f2tf32(p2);
            Ps[warp][gID + 8][nt * 8 + tig * 2 + 1] = f2tf32(p3);
        }
        psum0 += __shfl_xor_sync(0xffffffffu, psum0, 1);
        psum0 += __shfl_xor_sync(0xffffffffu, psum0, 2);
        psum1 += __shfl_xor_sync(0xffffffffu, psum1, 1);
        psum1 += __shfl_xor_sync(0xffffffffu, psum1, 2);
        l0 = l0 * corr0 + psum0;
        l1 = l1 * corr1 + psum1;

#pragma unroll
        for (int nt = 0; nt < 16; ++nt) {
            oacc[nt][0] *= corr0; oacc[nt][1] *= corr0;
            oacc[nt][2] *= corr1; oacc[nt][3] *= corr1;
        }
        __syncwarp();

#pragma unroll
        for (int kk = 0; kk < 8; ++kk) {
            unsigned pa[4];
            pa[0] = Ps[warp][gID    ][kk * 8 + tig];
            pa[1] = Ps[warp][gID + 8][kk * 8 + tig];
            pa[2] = Ps[warp][gID    ][kk * 8 + tig + 4];
            pa[3] = Ps[warp][gID + 8][kk * 8 + tig + 4];
#pragma unroll
            for (int nt = 0; nt < 16; ++nt) {
                unsigned bv[2];
                bv[0] = Vs[kk * 8 + tig    ][nt * 8 + gID];
                bv[1] = Vs[kk * 8 + tig + 4][nt * 8 + gID];
                mma_tf32(oacc[nt], pa, bv);
            }
        }
    }

    const float il0 = 1.f / l0;
    const float il1 = 1.f / l1;
    float* Og = O + ((size_t)(b * T + rowg0)) * DMODEL + h * DK;
#pragma unroll
    for (int nt = 0; nt < 16; ++nt) {
        const int col = nt * 8 + tig * 2;
        *(float2*)(Og + col) =
            make_float2(oacc[nt][0] * il0, oacc[nt][1] * il0);
        *(float2*)(Og + (size_t)8 * DMODEL + col) =
            make_float2(oacc[nt][2] * il1, oacc[nt][3] * il1);
    }
}

// ---------------------------------------------------------------------------
extern "C" void kernel_launch(void* const* d_in, const int* in_sizes, int n_in,
                              void* d_out, int out_size)
{
    (void)in_sizes; (void)n_in; (void)out_size;
    const float* x  = (const float*)d_in[0];
    const float* Wq = (const float*)d_in[2];
    const float* Wk = (const float*)d_in[3];
    const float* Wv = (const float*)d_in[4];
    const float* Wo = (const float*)d_in[5];
    float* out = (float*)d_out;

    float *Qb, *Kb, *Vb, *AO;
    cudaGetSymbolAddress((void**)&Qb, g_Q);
    cudaGetSymbolAddress((void**)&Kb, g_K);
    cudaGetSymbolAddress((void**)&Vb, g_V);
    cudaGetSymbolAddress((void**)&AO, g_AO);

    cudaFuncSetAttribute(attn_mma, cudaFuncAttributeMaxDynamicSharedMemorySize,
                         ATTN_SMEM_BYTES);

    const int M = B * T;           // 8192
    const int HALF = M / 2;        // 4096 rows = batches {0,1} / {2,3}

    cudaStream_t s2;
    cudaEvent_t evFork, evJoin, evH0, evO0;
    cudaStreamCreateWithFlags(&s2, cudaStreamNonBlocking);
    cudaEventCreateWithFlags(&evFork, cudaEventDisableTiming);
    cudaEventCreateWithFlags(&evJoin, cudaEventDisableTiming);
    cudaEventCreateWithFlags(&evH0,   cudaEventDisableTiming);
    cudaEventCreateWithFlags(&evO0,   cudaEventDisableTiming);

    cudaEventRecord(evFork, 0);
    cudaStreamWaitEvent(s2, evFork, 0);

    // KV projections on s2, Q projection on main stream (round-14 fork)
    gemm_tf32<<<dim3((KVH * DK) / 128, M / 128, 2), 256, 0, s2>>>(
        x, Wk, Wv, Kb, Vb, M, KVH * DK, DMODEL, 1, 0);
    cudaEventRecord(evJoin, s2);

    gemm_tf32<<<dim3(DMODEL / 128, M / 128, 1), 256>>>(
        x, Wq, Wq, Qb, Qb, M, DMODEL, DMODEL, 1, 1);

    cudaStreamWaitEvent(0, evJoin, 0);

    // Attention half 0 (batches 0,1)
    attn_mma<<<dim3((T / 64) * 2 * NH), 128, ATTN_SMEM_BYTES>>>(
        Qb, Kb, Vb, AO, 0, 2);
    cudaEventRecord(evH0, 0);

    // O-GEMM half 0 on s2, overlapping attention half 1
    cudaStreamWaitEvent(s2, evH0, 0);
    gemm_tf32<<<dim3(DMODEL / 128, HALF / 128, 1), 256, 0, s2>>>(
        AO, Wo, Wo, out, out, HALF, DMODEL, DMODEL, 0, 0);
    cudaEventRecord(evO0, s2);

    // Attention half 1 (batches 2,3) on main stream
    attn_mma<<<dim3((T / 64) * 2 * NH), 128, ATTN_SMEM_BYTES>>>(
        Qb, Kb, Vb, AO, 2, 2);

    // O-GEMM half 1 on main stream
    gemm_tf32<<<dim3(DMODEL / 128, HALF / 128, 1), 256>>>(
        AO + (size_t)HALF * DMODEL, Wo, Wo,
        out + (size_t)HALF * DMODEL, out + (size_t)HALF * DMODEL,
        HALF, DMODEL, DMODEL, 0, 0);

    // Join s2 back into the main stream before the graph ends
    cudaStreamWaitEvent(0, evO0, 0);

    cudaEventDestroy(evFork);
    cudaEventDestroy(evJoin);
    cudaEventDestroy(evH0);
    cudaEventDestroy(evO0);
    cudaStreamDestroy(s2);
}

// round 17
// speedup vs baseline: 1.0713x; 1.0300x over previous
#include <cuda_runtime.h>
#include <math.h>
#include <stdint.h>

#define B 4
#define T 2048
#define DMODEL 2048
#define NH 16
#define KVH 4
#define DK 128
#define GQA (NH / KVH)

__device__ float g_Q[(size_t)B * T * DMODEL];
__device__ float g_K[(size_t)B * T * KVH * DK];
__device__ float g_V[(size_t)B * T * KVH * DK];
__device__ float g_AO[(size_t)B * T * DMODEL];

__device__ __forceinline__ unsigned f2tf32(float x) {
    unsigned r;
    asm("cvt.rna.tf32.f32 %0, %1;" : "=r"(r) : "f"(x));
    return r;
}

__device__ __forceinline__ void mma_tf32(float c[4], const unsigned a[4], const unsigned b[2]) {
    asm volatile(
        "mma.sync.aligned.m16n8k8.row.col.f32.tf32.tf32.f32 "
        "{%0,%1,%2,%3}, {%4,%5,%6,%7}, {%8,%9}, {%0,%1,%2,%3};"
        : "+f"(c[0]), "+f"(c[1]), "+f"(c[2]), "+f"(c[3])
        : "r"(a[0]), "r"(a[1]), "r"(a[2]), "r"(a[3]), "r"(b[0]), "r"(b[1]));
}

__device__ __forceinline__ uint32_t smem_u32(const void* p) {
    return (uint32_t)__cvta_generic_to_shared(p);
}
#define CP_ASYNC16(dst, src) \
    asm volatile("cp.async.cg.shared.global [%0], [%1], 16;" :: "r"(dst), "l"(src))
#define CP_COMMIT() asm volatile("cp.async.commit_group;")
#define CP_WAIT1()  asm volatile("cp.async.wait_group 1;")
#define CP_WAIT0()  asm volatile("cp.async.wait_group 0;")

// ---------------------------------------------------------------------------
// C[M,N] = A[M,K] * W[N,K]^T, tf32 mma, cp.async 2-stage pipeline.
// Round-8 compute. Epilogue mode bits: 1=rope, 2=round-to-tf32, 4=scale(1/sqrt dk).
// Q: 7 (rope+scale+round), K: 3 (rope+round), V: 2 (round), O: 0 (raw).
// Rounded outputs make attention staging a pure byte copy (f2tf32 idempotent).
// ---------------------------------------------------------------------------
__global__ __launch_bounds__(256) void gemm_tf32(
    const float* __restrict__ A,
    const float* __restrict__ Wa, const float* __restrict__ Wb,
    float* __restrict__ Ca, float* __restrict__ Cb,
    int M, int N, int K, int modeA, int modeB)
{
    __shared__ float As[2][128][20];
    __shared__ float Bs[2][128][20];

    const float* __restrict__ W = blockIdx.z ? Wb : Wa;
    float* __restrict__ C       = blockIdx.z ? Cb : Ca;
    const int mode              = blockIdx.z ? modeB : modeA;

    const int tid  = threadIdx.x;
    const int bm   = blockIdx.y * 128;
    const int bn   = blockIdx.x * 128;
    const int warp = tid >> 5, lane = tid & 31;
    const int wm   = (warp & 1) * 64;
    const int wn   = (warp >> 1) * 32;
    const int gID  = lane >> 2, tig = lane & 3;

    float acc[4][4][4];
#pragma unroll
    for (int i = 0; i < 4; ++i)
#pragma unroll
        for (int j = 0; j < 4; ++j)
#pragma unroll
            for (int q = 0; q < 4; ++q) acc[i][j][q] = 0.f;

    const int ntiles = K >> 4;

    {
#pragma unroll
        for (int i = 0; i < 2; ++i) {
            const int idx = tid + i * 256;
            const int row = idx >> 2;
            const int c   = (idx & 3) << 2;
            CP_ASYNC16(smem_u32(&As[0][row][c]), A + (size_t)(bm + row) * K + c);
            CP_ASYNC16(smem_u32(&Bs[0][row][c]), W + (size_t)(bn + row) * K + c);
        }
        CP_COMMIT();
    }

    for (int tt = 0; tt < ntiles; ++tt) {
        const int st = tt & 1;
        if (tt + 1 < ntiles) {
            const int k0 = (tt + 1) << 4;
            const int s1 = (tt + 1) & 1;
#pragma unroll
            for (int i = 0; i < 2; ++i) {
                const int idx = tid + i * 256;
                const int row = idx >> 2;
                const int c   = (idx & 3) << 2;
                CP_ASYNC16(smem_u32(&As[s1][row][c]), A + (size_t)(bm + row) * K + k0 + c);
                CP_ASYNC16(smem_u32(&Bs[s1][row][c]), W + (size_t)(bn + row) * K + k0 + c);
            }
            CP_COMMIT();
            CP_WAIT1();
        } else {
            CP_WAIT0();
        }
        __syncthreads();

#pragma unroll
        for (int ks = 0; ks < 2; ++ks) {
            const int kk = ks * 8;
            unsigned af[4][4], bf[4][2];
#pragma unroll
            for (int mt = 0; mt < 4; ++mt) {
                const int m0 = wm + mt * 16;
                af[mt][0] = f2tf32(As[st][m0 + gID    ][kk + tig]);
                af[mt][1] = f2tf32(As[st][m0 + gID + 8][kk + tig]);
                af[mt][2] = f2tf32(As[st][m0 + gID    ][kk + tig + 4]);
                af[mt][3] = f2tf32(As[st][m0 + gID + 8][kk + tig + 4]);
            }
#pragma unroll
            for (int nt = 0; nt < 4; ++nt) {
                const int n0 = wn + nt * 8;
                bf[nt][0] = f2tf32(Bs[st][n0 + gID][kk + tig]);
                bf[nt][1] = f2tf32(Bs[st][n0 + gID][kk + tig + 4]);
            }
#pragma unroll
            for (int mt = 0; mt < 4; ++mt)
#pragma unroll
                for (int nt = 0; nt < 4; ++nt)
                    mma_tf32(acc[mt][nt], af[mt], bf[nt]);
        }
        __syncthreads();
    }

    if (mode & 1) {   // fused RoPE (bit-identical to reference math)
#pragma unroll
        for (int nt = 0; nt < 4; ++nt) {
            const int col  = bn + wn + nt * 8 + tig * 2;
            const float e  = (float)(col & 127) * (1.0f / 128.0f);
            const float inv_freq = exp2f(-e * 13.2877123795494f);   // log2(10000)
#pragma unroll
            for (int mt = 0; mt < 4; ++mt) {
                const int row0 = bm + wm + mt * 16 + gID;
                const int t0   = row0 & (T - 1);
                const int t1   = (row0 + 8) & (T - 1);
                float s0, c0, s1, c1;
                sincosf((float)t0 * inv_freq, &s0, &c0);
                sincosf((float)t1 * inv_freq, &s1, &c1);
                const float x1a = acc[mt][nt][0], x2a = acc[mt][nt][1];
                acc[mt][nt][0] = x1a * c0 - x2a * s0;
                acc[mt][nt][1] = x1a * s0 + x2a * c0;
                const float x1b = acc[mt][nt][2], x2b = acc[mt][nt][3];
                acc[mt][nt][2] = x1b * c1 - x2b * s1;
                acc[mt][nt][3] = x1b * s1 + x2b * c1;
            }
        }
    }
    if (mode & 4) {   // fold 1/sqrt(dk) into Q (moved from attention staging)
        const float scale = 0.08838834764831845f;
#pragma unroll
        for (int mt = 0; mt < 4; ++mt)
#pragma unroll
            for (int nt = 0; nt < 4; ++nt)
#pragma unroll
                for (int q = 0; q < 4; ++q) acc[mt][nt][q] *= scale;
    }
    if (mode & 2) {   // round to tf32-valued fp32 (moved from attention staging)
#pragma unroll
        for (int mt = 0; mt < 4; ++mt)
#pragma unroll
            for (int nt = 0; nt < 4; ++nt)
#pragma unroll
                for (int q = 0; q < 4; ++q)
                    acc[mt][nt][q] = __uint_as_float(f2tf32(acc[mt][nt][q]));
    }

#pragma unroll
    for (int mt = 0; mt < 4; ++mt) {
#pragma unroll
        for (int nt = 0; nt < 4; ++nt) {
            const int row0 = bm + wm + mt * 16 + gID;
            const int col  = bn + wn + nt * 8 + tig * 2;
            float2* p0 = (float2*)(C + (size_t)row0 * N + col);
            float2* p1 = (float2*)(C + (size_t)(row0 + 8) * N + col);
            *p0 = make_float2(acc[mt][nt][0], acc[mt][nt][1]);
            *p1 = make_float2(acc[mt][nt][2], acc[mt][nt][3]);
        }
    }
}

// ---------------------------------------------------------------------------
// Tensor-core causal GQA flash attention, 64q x 64k tiles. Q/K/V arrive
// PRE-ROUNDED (tf32-valued; Q pre-scaled) -> staging is pure cp.async bulk
// copy: no LDG->reg, no CVT, no STS. Compute identical to round 14/16.
// ---------------------------------------------------------------------------
#define KS_STRIDE 132
#define VS_STRIDE 136
#define PS_STRIDE 68
#define ATTN_SMEM_WORDS (64 * KS_STRIDE + 64 * VS_STRIDE + 4 * 16 * PS_STRIDE)
#define ATTN_SMEM_BYTES (ATTN_SMEM_WORDS * 4)

__global__ __launch_bounds__(128) void attn_mma(
    const float* __restrict__ Q, const float* __restrict__ K,
    const float* __restrict__ V, float* __restrict__ O,
    int b_off, int nb)
{
    extern __shared__ unsigned dsm[];
    unsigned (*Ks)[KS_STRIDE] = (unsigned(*)[KS_STRIDE])dsm;
    unsigned (*Vs)[VS_STRIDE] = (unsigned(*)[VS_STRIDE])(dsm + 64 * KS_STRIDE);
    unsigned (*Ps)[16][PS_STRIDE] =
        (unsigned(*)[16][PS_STRIDE])(dsm + 64 * KS_STRIDE + 64 * VS_STRIDE);

    const int bid    = blockIdx.x;
    const int combos = nb * NH;
    const int qtile  = (T / 64 - 1) - (bid / combos);   // heavy q-tiles first
    const int bh     = bid % combos;
    const int b      = b_off + bh / NH;
    const int h      = bh % NH;
    const int kvh    = h / GQA;

    const int tid  = threadIdx.x;
    const int warp = tid >> 5, lane = tid & 31;
    const int gID  = lane >> 2, tig = lane & 3;

    const int qrow0 = qtile * 64;

    // Stage Q (pre-scaled, pre-rounded) via cp.async — raw bit copy.
    {
        const float* Qg = Q + ((size_t)(b * T + qrow0)) * DMODEL + h * DK;
#pragma unroll
        for (int i = 0; i < 16; ++i) {
            const int idx = i * 128 + tid;
            const int r   = idx >> 5;
            const int c4  = (idx & 31) << 2;
            CP_ASYNC16(smem_u32(&Ks[r][c4]), Qg + (size_t)r * DMODEL + c4);
        }
        CP_COMMIT();
        CP_WAIT0();
    }
    __syncthreads();

    unsigned qa[16][4];
    {
        const int m0 = warp * 16;
#pragma unroll
        for (int kk = 0; kk < 16; ++kk) {
            qa[kk][0] = Ks[m0 + gID    ][kk * 8 + tig];
            qa[kk][1] = Ks[m0 + gID + 8][kk * 8 + tig];
            qa[kk][2] = Ks[m0 + gID    ][kk * 8 + tig + 4];
            qa[kk][3] = Ks[m0 + gID + 8][kk * 8 + tig + 4];
        }
    }

    float oacc[16][4];
#pragma unroll
    for (int i = 0; i < 16; ++i)
#pragma unroll
        for (int j = 0; j < 4; ++j) oacc[i][j] = 0.f;

    float m0s = -INFINITY, m1s = -INFINITY, l0 = 0.f, l1 = 0.f;
    const int rowg0 = qrow0 + warp * 16 + gID;
    const int rowg1 = rowg0 + 8;

    const size_t kvStride = (size_t)KVH * DK;   // 512
    const int ntiles = qtile + 1;

    for (int tile = 0; tile < ntiles; ++tile) {
        const int kt = tile * 64;
        __syncthreads();   // prior Ks/Vs readers done before restaging
        {
            const float* Kg = K + ((size_t)(b * T + kt)) * kvStride + kvh * DK;
            const float* Vg = V + ((size_t)(b * T + kt)) * kvStride + kvh * DK;
#pragma unroll
            for (int i = 0; i < 16; ++i) {
                const int idx = i * 128 + tid;
                const int r   = idx >> 5;
                const int c4  = (idx & 31) << 2;
                CP_ASYNC16(smem_u32(&Ks[r][c4]), Kg + (size_t)r * kvStride + c4);
                CP_ASYNC16(smem_u32(&Vs[r][c4]), Vg + (size_t)r * kvStride + c4);
            }
            CP_COMMIT();
            CP_WAIT0();
        }
        __syncthreads();

        // S = Q*K^T  (m16 x n64, k=128)
        float sacc[8][4];
#pragma unroll
        for (int nt = 0; nt < 8; ++nt)
#pragma unroll
            for (int e = 0; e < 4; ++e) sacc[nt][e] = 0.f;

#pragma unroll
        for (int kk = 0; kk < 16; ++kk) {
            unsigned bfr[8][2];
#pragma unroll
            for (int nt = 0; nt < 8; ++nt) {
                bfr[nt][0] = Ks[nt * 8 + gID][kk * 8 + tig];
                bfr[nt][1] = Ks[nt * 8 + gID][kk * 8 + tig + 4];
            }
#pragma unroll
            for (int nt = 0; nt < 8; ++nt)
                mma_tf32(sacc[nt], qa[kk], bfr[nt]);
        }

        const bool diag = (tile == ntiles - 1);
        float rmax0 = -INFINITY, rmax1 = -INFINITY;
#pragma unroll
        for (int nt = 0; nt < 8; ++nt) {
            if (diag) {
                const int colg = kt + nt * 8 + tig * 2;
                if (colg     > rowg0) sacc[nt][0] = -1e30f;
                if (colg + 1 > rowg0) sacc[nt][1] = -1e30f;
                if (colg     > rowg1) sacc[nt][2] = -1e30f;
                if (colg + 1 > rowg1) sacc[nt][3] = -1e30f;
            }
            rmax0 = fmaxf(rmax0, fmaxf(sacc[nt][0], sacc[nt][1]));
            rmax1 = fmaxf(rmax1, fmaxf(sacc[nt][2], sacc[nt][3]));
        }
        rmax0 = fmaxf(rmax0, __shfl_xor_sync(0xffffffffu, rmax0, 1));
        rmax0 = fmaxf(rmax0, __shfl_xor_sync(0xffffffffu, rmax0, 2));
        rmax1 = fmaxf(rmax1, __shfl_xor_sync(0xffffffffu, rmax1, 1));
        rmax1 = fmaxf(rmax1, __shfl_xor_sync(0xffffffffu, rmax1, 2));

        const float mn0 = fmaxf(m0s, rmax0);
        const float mn1 = fmaxf(m1s, rmax1);
        const float corr0 = __expf(m0s - mn0);
        const float corr1 = __expf(m1s - mn1);
        m0s = mn0; m1s = mn1;

        __syncwarp();
        float psum0 = 0.f, psum1 = 0.f;
#pragma unroll
        for (int nt = 0; nt < 8; ++nt) {
            const float p0 = __expf(sacc[nt][0] - mn0);
            const float p1 = __expf(sacc[nt][1] - mn0);
            const float p2 = __expf(sacc[nt][2] - mn1);
            const float p3 = __expf(sacc[nt][3] - mn1);
            psum0 += p0 + p1;
            psum1 += p2 + p3;
            Ps[warp][gID    ][nt * 8 + tig * 2    ] = f2tf32(p0);
            Ps[warp][gID    ][nt * 8 + tig * 2 + 1] = f2tf32(p1);
            Ps[warp][gID + 8][nt * 8 + tig * 2    ] = f2tf32(p2);
            Ps[warp][gID + 8][nt * 8 + tig * 2 + 1] = f2tf32(p3);
        }
        psum0 += __shfl_xor_sync(0xffffffffu, psum0, 1);
        psum0 += __shfl_xor_sync(0xffffffffu, psum0, 2);
        psum1 += __shfl_xor_sync(0xffffffffu, psum1, 1);
        psum1 += __shfl_xor_sync(0xffffffffu, psum1, 2);
        l0 = l0 * corr0 + psum0;
        l1 = l1 * corr1 + psum1;

#pragma unroll
        for (int nt = 0; nt < 16; ++nt) {
            oacc[nt][0] *= corr0; oacc[nt][1] *= corr0;
            oacc[nt][2] *= corr1; oacc[nt][3] *= corr1;
        }
        __syncwarp();

        // O += P*V  (m16 x n128, k=64)
#pragma unroll
        for (int kk = 0; kk < 8; ++kk) {
            unsigned pa[4];
            pa[0] = Ps[warp][gID    ][kk * 8 + tig];
            pa[1] = Ps[warp][gID + 8][kk * 8 + tig];
            pa[2] = Ps[warp][gID    ][kk * 8 + tig + 4];
            pa[3] = Ps[warp][gID + 8][kk * 8 + tig + 4];
#pragma unroll
            for (int nt = 0; nt < 16; ++nt) {
                unsigned bv[2];
                bv[0] = Vs[kk * 8 + tig    ][nt * 8 + gID];
                bv[1] = Vs[kk * 8 + tig + 4][nt * 8 + gID];
                mma_tf32(oacc[nt], pa, bv);
            }
        }
    }

    const float il0 = 1.f / l0;
    const float il1 = 1.f / l1;
    float* Og = O + ((size_t)(b * T + rowg0)) * DMODEL + h * DK;
#pragma unroll
    for (int nt = 0; nt < 16; ++nt) {
        const int col = nt * 8 + tig * 2;
        *(float2*)(Og + col) =
            make_float2(oacc[nt][0] * il0, oacc[nt][1] * il0);
        *(float2*)(Og + (size_t)8 * DMODEL + col) =
            make_float2(oacc[nt][2] * il1, oacc[nt][3] * il1);
    }
}

// ---------------------------------------------------------------------------
extern "C" void kernel_launch(void* const* d_in, const int* in_sizes, int n_in,
                              void* d_out, int out_size)
{
    (void)in_sizes; (void)n_in; (void)out_size;
    const float* x  = (const float*)d_in[0];
    const float* Wq = (const float*)d_in[2];
    const float* Wk = (const float*)d_in[3];
    const float* Wv = (const float*)d_in[4];
    const float* Wo = (const float*)d_in[5];
    float* out = (float*)d_out;

    float *Qb, *Kb, *Vb, *AO;
    cudaGetSymbolAddress((void**)&Qb, g_Q);
    cudaGetSymbolAddress((void**)&Kb, g_K);
    cudaGetSymbolAddress((void**)&Vb, g_V);
    cudaGetSymbolAddress((void**)&AO, g_AO);

    cudaFuncSetAttribute(attn_mma, cudaFuncAttributeMaxDynamicSharedMemorySize,
                         ATTN_SMEM_BYTES);

    const int M = B * T;           // 8192
    const int HALF = M / 2;        // batches {0,1} / {2,3}

    cudaStream_t s2;
    cudaEvent_t evFork, evJoin, evH0, evO0;
    cudaStreamCreateWithFlags(&s2, cudaStreamNonBlocking);
    cudaEventCreateWithFlags(&evFork, cudaEventDisableTiming);
    cudaEventCreateWithFlags(&evJoin, cudaEventDisableTiming);
    cudaEventCreateWithFlags(&evH0,   cudaEventDisableTiming);
    cudaEventCreateWithFlags(&evO0,   cudaEventDisableTiming);

    cudaEventRecord(evFork, 0);
    cudaStreamWaitEvent(s2, evFork, 0);

    // K (rope+round=3) + V (round=2) on s2
    gemm_tf32<<<dim3((KVH * DK) / 128, M / 128, 2), 256, 0, s2>>>(
        x, Wk, Wv, Kb, Vb, M, KVH * DK, DMODEL, 3, 2);
    cudaEventRecord(evJoin, s2);

    // Q (rope+round+scale=7) on main stream
    gemm_tf32<<<dim3(DMODEL / 128, M / 128, 1), 256>>>(
        x, Wq, Wq, Qb, Qb, M, DMODEL, DMODEL, 7, 7);

    cudaStreamWaitEvent(0, evJoin, 0);

    // Attention half 0 (batches 0,1)
    attn_mma<<<dim3((T / 64) * 2 * NH), 128, ATTN_SMEM_BYTES>>>(
        Qb, Kb, Vb, AO, 0, 2);
    cudaEventRecord(evH0, 0);

    // O-GEMM half 0 on s2, overlapping attention half 1
    cudaStreamWaitEvent(s2, evH0, 0);
    gemm_tf32<<<dim3(DMODEL / 128, HALF / 128, 1), 256, 0, s2>>>(
        AO, Wo, Wo, out, out, HALF, DMODEL, DMODEL, 0, 0);
    cudaEventRecord(evO0, s2);

    // Attention half 1 (batches 2,3)
    attn_mma<<<dim3((T / 64) * 2 * NH), 128, ATTN_SMEM_BYTES>>>(
        Qb, Kb, Vb, AO, 2, 2);

    // O-GEMM half 1 on main stream
    gemm_tf32<<<dim3(DMODEL / 128, HALF / 128, 1), 256>>>(
        AO + (size_t)HALF * DMODEL, Wo, Wo,
        out + (size_t)HALF * DMODEL, out + (size_t)HALF * DMODEL,
        HALF, DMODEL, DMODEL, 0, 0);

    cudaStreamWaitEvent(0, evO0, 0);

    cudaEventDestroy(evFork);
    cudaEventDestroy(evJoin);
    cudaEventDestroy(evH0);
    cudaEventDestroy(evO0);
    cudaStreamDestroy(s2);
}